// round 1
// baseline (speedup 1.0000x reference)
#include <cuda_runtime.h>
#include <stdint.h>

#define BATCH 64
#define PIX   784
#define DIMS  10000
#define LVLS  256
#define NCLS  10
#define W313  313          // ceil(10000/32)
#define WPAD  320          // padded word count
#define PCH   4            // p-chunks
#define PPC   196          // pixels per chunk (784/4)

// ---- scratch (static device globals; no allocations anywhere) ----
__device__ uint32_t g_pos_bits[PIX  * WPAD];   // sign bits of position  [p][w]
__device__ uint32_t g_lvl_bits[LVLS * WPAD];   // sign bits of levels    [l][w]
__device__ uint8_t  g_idx[BATCH * PIX];        // quantized level index  [b][p]
__device__ uint32_t g_part[BATCH * WPAD * PCH * 8]; // partial bit-plane counters

// ------------------------------------------------------------------
// K0: pack sign bits of position (rows 0..783) and level (rows 784..1039)
// ------------------------------------------------------------------
__global__ void __launch_bounds__(256) pack_bits(const float* __restrict__ pos,
                                                 const float* __restrict__ lvl) {
    int row = blockIdx.x;
    const float* src;
    uint32_t* dst;
    if (row < PIX) { src = pos + (size_t)row * DIMS; dst = g_pos_bits + row * WPAD; }
    else           { src = lvl + (size_t)(row - PIX) * DIMS; dst = g_lvl_bits + (row - PIX) * WPAD; }

    int lane = threadIdx.x & 31;
    int warp = threadIdx.x >> 5;
    for (int w = warp; w < W313; w += 8) {
        int d = w * 32 + lane;
        float v = (d < DIMS) ? src[d] : 1.0f;   // padding bits -> 0
        uint32_t m = __ballot_sync(0xffffffffu, v < 0.0f);
        if (lane == 0) dst[w] = m;
    }
}

// ------------------------------------------------------------------
// K1: quantize pixel intensities to level indices (round-half-even, clamp)
// ------------------------------------------------------------------
__global__ void __launch_bounds__(256) compute_idx(const float* __restrict__ x) {
    int tid = blockIdx.x * blockDim.x + threadIdx.x;
    if (tid >= BATCH * PIX) return;
    int i = __float2int_rn(x[tid] * 255.0f);   // round-nearest-even like jnp.round
    i = max(0, min(255, i));
    g_idx[tid] = (uint8_t)i;
}

// ------------------------------------------------------------------
// K2: main bind+bundle via XOR + CSA bit-plane counters.
// Block = 256 threads: warp -> batch (8 per block), lane -> dim-word (32 per block).
// Grid = (10 word-blocks, 8 batch-blocks, 4 p-chunks).
// ------------------------------------------------------------------
__global__ void __launch_bounds__(256) hdc_main() {
    __shared__ uint32_t s_lvl[LVLS * 32];   // 32 KB, lane-major -> conflict-free gather

    int lane   = threadIdx.x & 31;
    int warp   = threadIdx.x >> 5;
    int wblock = blockIdx.x;                // 0..9
    int bblock = blockIdx.y;                // 0..7
    int pc     = blockIdx.z;                // 0..3
    int w = wblock * 32 + lane;             // padded word index (< 320)

    // stage the level-bit column slice: s_lvl[l*32+lane] = g_lvl_bits[l][w]
    for (int l = warp; l < LVLS; l += 8)
        s_lvl[l * 32 + lane] = g_lvl_bits[l * WPAD + w];
    __syncthreads();

    int b = bblock * 8 + warp;
    const uint8_t*  idxr = g_idx + b * PIX + pc * PPC;     // warp-uniform stream
    const uint32_t* posr = g_pos_bits + (pc * PPC) * WPAD + w;

    // bit-plane counters: value per column <= 196 -> 8 planes
    uint32_t ones = 0, twos = 0, c2 = 0, c3 = 0, c4 = 0, c5 = 0, c6 = 0, c7 = 0;

    for (int q = 0; q < PPC / 4; q++) {
        uint32_t i4 = *(const uint32_t*)(idxr + q * 4);    // 4 level indices (uniform)
        uint32_t x0 = s_lvl[((i4      ) & 255u) * 32 + lane] ^ posr[(q * 4 + 0) * WPAD];
        uint32_t x1 = s_lvl[((i4 >>  8) & 255u) * 32 + lane] ^ posr[(q * 4 + 1) * WPAD];
        uint32_t x2 = s_lvl[((i4 >> 16) & 255u) * 32 + lane] ^ posr[(q * 4 + 2) * WPAD];
        uint32_t x3 = s_lvl[((i4 >> 24)       ) * 32 + lane] ^ posr[(q * 4 + 3) * WPAD];

        // CSA: x0+x1+x2 -> (h01 carry, l01 sum)
        uint32_t t0  = x0 ^ x1;
        uint32_t l01 = t0 ^ x2;
        uint32_t h01 = (x0 & x1) | (t0 & x2);
        // ones += l01 + x3
        uint32_t t1 = ones ^ l01;
        uint32_t ca = (ones & l01) | (t1 & x3);
        ones = t1 ^ x3;
        // twos += h01 + ca
        uint32_t t2 = twos ^ h01;
        uint32_t cb = (twos & h01) | (t2 & ca);
        twos = t2 ^ ca;
        // ripple cb through the upper planes
        uint32_t cr = cb, t;
        t = c2 & cr; c2 ^= cr; cr = t;
        t = c3 & cr; c3 ^= cr; cr = t;
        t = c4 & cr; c4 ^= cr; cr = t;
        t = c5 & cr; c5 ^= cr; cr = t;
        c6 ^= cr ^ (c7 & 0u);  // keep simple:
        // NOTE: proper ripple for c6/c7:
        t = c6 & cr;           // (cr already xor'ed into c6 above is WRONG — redo below)
        (void)t;
    }
    // The c6 handling above is intentionally rewritten correctly here is NOT possible
    // post-loop; see corrected loop below.
    // ---- (unreachable placeholder removed by recompile-safe structure) ----

    uint32_t* outp = g_part + ((size_t)(b * WPAD + w) * PCH + pc) * 8;
    outp[0] = ones; outp[1] = twos; outp[2] = c2; outp[3] = c3;
    outp[4] = c4;   outp[5] = c5;   outp[6] = c6; outp[7] = c7;
}

// ------------------------------------------------------------------
// NOTE: hdc_main above had a ripple bug; define the corrected kernel and use it.
// ------------------------------------------------------------------
__global__ void __launch_bounds__(256) hdc_main_v2() {
    __shared__ uint32_t s_lvl[LVLS * 32];

    int lane   = threadIdx.x & 31;
    int warp   = threadIdx.x >> 5;
    int wblock = blockIdx.x;
    int bblock = blockIdx.y;
    int pc     = blockIdx.z;
    int w = wblock * 32 + lane;

    for (int l = warp; l < LVLS; l += 8)
        s_lvl[l * 32 + lane] = g_lvl_bits[l * WPAD + w];
    __syncthreads();

    int b = bblock * 8 + warp;
    const uint8_t*  idxr = g_idx + b * PIX + pc * PPC;
    const uint32_t* posr = g_pos_bits + (pc * PPC) * WPAD + w;

    uint32_t ones = 0, twos = 0, c2 = 0, c3 = 0, c4 = 0, c5 = 0, c6 = 0, c7 = 0;

    for (int q = 0; q < PPC / 4; q++) {
        uint32_t i4 = *(const uint32_t*)(idxr + q * 4);
        uint32_t x0 = s_lvl[((i4      ) & 255u) * 32 + lane] ^ posr[(q * 4 + 0) * WPAD];
        uint32_t x1 = s_lvl[((i4 >>  8) & 255u) * 32 + lane] ^ posr[(q * 4 + 1) * WPAD];
        uint32_t x2 = s_lvl[((i4 >> 16) & 255u) * 32 + lane] ^ posr[(q * 4 + 2) * WPAD];
        uint32_t x3 = s_lvl[((i4 >> 24)       ) * 32 + lane] ^ posr[(q * 4 + 3) * WPAD];

        uint32_t t0  = x0 ^ x1;
        uint32_t l01 = t0 ^ x2;
        uint32_t h01 = (x0 & x1) | (t0 & x2);
        uint32_t t1 = ones ^ l01;
        uint32_t ca = (ones & l01) | (t1 & x3);
        ones = t1 ^ x3;
        uint32_t t2 = twos ^ h01;
        uint32_t cb = (twos & h01) | (t2 & ca);
        twos = t2 ^ ca;
        uint32_t cr = cb, t;
        t = c2 & cr; c2 ^= cr; cr = t;
        t = c3 & cr; c3 ^= cr; cr = t;
        t = c4 & cr; c4 ^= cr; cr = t;
        t = c5 & cr; c5 ^= cr; cr = t;
        t = c6 & cr; c6 ^= cr; cr = t;
        c7 ^= cr;
    }

    uint32_t* outp = g_part + ((size_t)(b * WPAD + w) * PCH + pc) * 8;
    outp[0] = ones; outp[1] = twos; outp[2] = c2; outp[3] = c3;
    outp[4] = c4;   outp[5] = c5;   outp[6] = c6; outp[7] = c7;
}

// ------------------------------------------------------------------
// K3: merge partial planes, threshold (cnt >= 392 -> enc = -1), classify.
// One block per batch element; deterministic in-block reduction.
// ------------------------------------------------------------------
template <int N>
__device__ __forceinline__ void plane_add(uint32_t* dst, const uint32_t* a, const uint32_t* b) {
    uint32_t carry = 0;
#pragma unroll
    for (int i = 0; i < N; i++) {
        uint32_t t = a[i] ^ b[i];
        dst[i] = t ^ carry;
        carry = (a[i] & b[i]) | (t & carry);
    }
    dst[N] = carry;
}

__global__ void __launch_bounds__(256) finalize(const float* __restrict__ Wc,
                                                float* __restrict__ out) {
    int b = blockIdx.x;
    __shared__ float red[NCLS * 256];

    float acc[NCLS];
#pragma unroll
    for (int c = 0; c < NCLS; c++) acc[c] = 0.0f;

    for (int w = threadIdx.x; w < W313; w += 256) {
        const uint32_t* pp = g_part + (size_t)(b * WPAD + w) * (PCH * 8);
        uint32_t q0[8], q1[8], q2[8], q3[8];
#pragma unroll
        for (int i = 0; i < 8; i++) {
            q0[i] = pp[i]; q1[i] = pp[8 + i]; q2[i] = pp[16 + i]; q3[i] = pp[24 + i];
        }
        uint32_t A[9], Bp[9], Cc[10];
        plane_add<8>(A, q0, q1);
        plane_add<8>(Bp, q2, q3);
        plane_add<9>(Cc, A, Bp);

        // bitwise compare: cnt >= 392 ?  (392 = 0b0110001000)
        uint32_t gt = 0, eq = 0xffffffffu;
#pragma unroll
        for (int i = 9; i >= 0; i--) {
            if ((392 >> i) & 1) { eq &= Cc[i]; }
            else { gt |= eq & Cc[i]; eq &= ~Cc[i]; }
        }
        uint32_t neg = gt | eq;   // enc = -1 where set

        int dbase = w * 32;
        int jmax = min(32, DIMS - dbase);
        for (int j = 0; j < jmax; j++) {
            float s = ((neg >> j) & 1u) ? -1.0f : 1.0f;
#pragma unroll
            for (int c = 0; c < NCLS; c++)
                acc[c] = fmaf(s, Wc[c * DIMS + dbase + j], acc[c]);
        }
    }

#pragma unroll
    for (int c = 0; c < NCLS; c++) red[c * 256 + threadIdx.x] = acc[c];
    __syncthreads();
    for (int off = 128; off > 0; off >>= 1) {
        if (threadIdx.x < off) {
#pragma unroll
            for (int c = 0; c < NCLS; c++)
                red[c * 256 + threadIdx.x] += red[c * 256 + threadIdx.x + off];
        }
        __syncthreads();
    }
    if (threadIdx.x < NCLS) out[b * NCLS + threadIdx.x] = red[threadIdx.x * 256];
}

// ------------------------------------------------------------------
extern "C" void kernel_launch(void* const* d_in, const int* in_sizes, int n_in,
                              void* d_out, int out_size) {
    const float* x   = (const float*)d_in[0];   // [64,28,28]
    const float* pos = (const float*)d_in[1];   // [784,10000]
    const float* lvl = (const float*)d_in[2];   // [256,10000]
    const float* cw  = (const float*)d_in[3];   // [10,10000]
    float* out = (float*)d_out;                 // [64,10]

    pack_bits<<<PIX + LVLS, 256>>>(pos, lvl);
    compute_idx<<<(BATCH * PIX + 255) / 256, 256>>>(x);
    hdc_main_v2<<<dim3((WPAD / 32), BATCH / 8, PCH), 256>>>();
    finalize<<<BATCH, 256>>>(cw, out);
}

// round 2
// speedup vs baseline: 2.1104x; 2.1104x over previous
#include <cuda_runtime.h>
#include <stdint.h>

#define BATCH 64
#define PIX   784
#define DIMS  10000
#define LVLS  256
#define NCLS  10
#define W313  313          // ceil(10000/32)
#define WPAD  320          // padded word count
#define PCH   4            // p-chunks
#define PPC   196          // pixels per chunk (784/4)

// ---- scratch (static device globals; no allocations anywhere) ----
__device__ uint32_t g_pos_bits[PIX  * WPAD];        // sign bits of position  [p][w]
__device__ uint32_t g_lvl_bits[LVLS * WPAD];        // sign bits of levels    [l][w]
__device__ uint8_t  g_idx[BATCH * PIX];             // quantized level index  [b][p]
__device__ uint32_t g_part[BATCH * WPAD * PCH * 8]; // partial bit-plane counters
__device__ uint32_t g_enc[BATCH * WPAD];            // packed enc sign bits (1 = -1)

// ------------------------------------------------------------------
// K0: pack sign bits of position (rows 0..783) and level (rows 784..1039)
// ------------------------------------------------------------------
__global__ void __launch_bounds__(256) pack_bits(const float* __restrict__ pos,
                                                 const float* __restrict__ lvl) {
    int row = blockIdx.x;
    const float* src;
    uint32_t* dst;
    if (row < PIX) { src = pos + (size_t)row * DIMS; dst = g_pos_bits + row * WPAD; }
    else           { src = lvl + (size_t)(row - PIX) * DIMS; dst = g_lvl_bits + (row - PIX) * WPAD; }

    int lane = threadIdx.x & 31;
    int warp = threadIdx.x >> 5;
    for (int w = warp; w < W313; w += 8) {
        int d = w * 32 + lane;
        float v = (d < DIMS) ? src[d] : 1.0f;   // padding bits -> 0
        uint32_t m = __ballot_sync(0xffffffffu, v < 0.0f);
        if (lane == 0) dst[w] = m;
    }
}

// ------------------------------------------------------------------
// K1: quantize pixel intensities to level indices (round-nearest-even, clamp)
// ------------------------------------------------------------------
__global__ void __launch_bounds__(256) compute_idx(const float* __restrict__ x) {
    int tid = blockIdx.x * blockDim.x + threadIdx.x;
    if (tid >= BATCH * PIX) return;
    int i = __float2int_rn(x[tid] * 255.0f);
    i = max(0, min(255, i));
    g_idx[tid] = (uint8_t)i;
}

// ------------------------------------------------------------------
// K2: main bind+bundle via XOR + CSA bit-plane counters.
// Block = 256 threads: warp -> batch (8 per block), lane -> dim-word (32 per block).
// Grid = (10 word-blocks, 8 batch-blocks, 4 p-chunks).
// ------------------------------------------------------------------
__global__ void __launch_bounds__(256) hdc_main() {
    __shared__ uint32_t s_lvl[LVLS * 32];   // 32 KB, lane-major -> conflict-free gather

    int lane   = threadIdx.x & 31;
    int warp   = threadIdx.x >> 5;
    int wblock = blockIdx.x;
    int bblock = blockIdx.y;
    int pc     = blockIdx.z;
    int w = wblock * 32 + lane;

    for (int l = warp; l < LVLS; l += 8)
        s_lvl[l * 32 + lane] = g_lvl_bits[l * WPAD + w];
    __syncthreads();

    int b = bblock * 8 + warp;
    const uint8_t*  idxr = g_idx + b * PIX + pc * PPC;      // warp-uniform stream
    const uint32_t* posr = g_pos_bits + (pc * PPC) * WPAD + w;

    uint32_t ones = 0, twos = 0, c2 = 0, c3 = 0, c4 = 0, c5 = 0, c6 = 0, c7 = 0;

    for (int q = 0; q < PPC / 4; q++) {
        uint32_t i4 = *(const uint32_t*)(idxr + q * 4);
        uint32_t x0 = s_lvl[((i4      ) & 255u) * 32 + lane] ^ posr[(q * 4 + 0) * WPAD];
        uint32_t x1 = s_lvl[((i4 >>  8) & 255u) * 32 + lane] ^ posr[(q * 4 + 1) * WPAD];
        uint32_t x2 = s_lvl[((i4 >> 16) & 255u) * 32 + lane] ^ posr[(q * 4 + 2) * WPAD];
        uint32_t x3 = s_lvl[((i4 >> 24)       ) * 32 + lane] ^ posr[(q * 4 + 3) * WPAD];

        uint32_t t0  = x0 ^ x1;
        uint32_t l01 = t0 ^ x2;
        uint32_t h01 = (x0 & x1) | (t0 & x2);
        uint32_t t1 = ones ^ l01;
        uint32_t ca = (ones & l01) | (t1 & x3);
        ones = t1 ^ x3;
        uint32_t t2 = twos ^ h01;
        uint32_t cb = (twos & h01) | (t2 & ca);
        twos = t2 ^ ca;
        uint32_t cr = cb, t;
        t = c2 & cr; c2 ^= cr; cr = t;
        t = c3 & cr; c3 ^= cr; cr = t;
        t = c4 & cr; c4 ^= cr; cr = t;
        t = c5 & cr; c5 ^= cr; cr = t;
        t = c6 & cr; c6 ^= cr; cr = t;
        c7 ^= cr;
    }

    uint32_t* outp = g_part + ((size_t)(b * WPAD + w) * PCH + pc) * 8;
    outp[0] = ones; outp[1] = twos; outp[2] = c2; outp[3] = c3;
    outp[4] = c4;   outp[5] = c5;   outp[6] = c6; outp[7] = c7;
}

// ------------------------------------------------------------------
// K3a: merge the 4 partial 8-plane counters and threshold vs 392.
// One THREAD per (b, w): reads 128 contiguous bytes, writes one word.
// ------------------------------------------------------------------
template <int N>
__device__ __forceinline__ void plane_add(uint32_t* dst, const uint32_t* a, const uint32_t* b) {
    uint32_t carry = 0;
#pragma unroll
    for (int i = 0; i < N; i++) {
        uint32_t t = a[i] ^ b[i];
        dst[i] = t ^ carry;
        carry = (a[i] & b[i]) | (t & carry);
    }
    dst[N] = carry;
}

__global__ void __launch_bounds__(256) merge_threshold() {
    int tid = blockIdx.x * 256 + threadIdx.x;
    if (tid >= BATCH * W313) return;
    int b = tid / W313;
    int w = tid - b * W313;

    const uint4* pp = (const uint4*)(g_part + (size_t)(b * WPAD + w) * (PCH * 8));
    uint32_t q[32];
#pragma unroll
    for (int i = 0; i < 8; i++) {
        uint4 v = pp[i];
        q[i * 4 + 0] = v.x; q[i * 4 + 1] = v.y; q[i * 4 + 2] = v.z; q[i * 4 + 3] = v.w;
    }

    uint32_t A[9], Bp[9], Cc[10];
    plane_add<8>(A,  q,      q + 8);
    plane_add<8>(Bp, q + 16, q + 24);
    plane_add<9>(Cc, A, Bp);

    // bitwise compare per column: cnt >= 392 (392 = 0b0110001000)
    uint32_t gt = 0, eq = 0xffffffffu;
#pragma unroll
    for (int i = 9; i >= 0; i--) {
        if ((392 >> i) & 1) { eq &= Cc[i]; }
        else { gt |= eq & Cc[i]; eq &= ~Cc[i]; }
    }
    g_enc[b * WPAD + w] = gt | eq;   // bit set -> enc = -1
}

// ------------------------------------------------------------------
// K3b: classify — grid (BATCH, NCLS), coalesced W reads, XOR sign flip.
// ------------------------------------------------------------------
__global__ void __launch_bounds__(256) classify(const float* __restrict__ Wc,
                                                float* __restrict__ out) {
    int b = blockIdx.x;
    int c = blockIdx.y;
    const float* wrow = Wc + (size_t)c * DIMS;
    const uint32_t* encp = g_enc + b * WPAD;

    float acc = 0.0f;
    for (int d = threadIdx.x; d < DIMS; d += 256) {
        uint32_t neg  = encp[d >> 5];
        uint32_t flip = ((neg >> (d & 31)) & 1u) << 31;   // sign-bit flip
        acc += __uint_as_float(__float_as_uint(wrow[d]) ^ flip);
    }

    // warp reduce
#pragma unroll
    for (int off = 16; off > 0; off >>= 1)
        acc += __shfl_down_sync(0xffffffffu, acc, off);

    __shared__ float red[8];
    int lane = threadIdx.x & 31, warp = threadIdx.x >> 5;
    if (lane == 0) red[warp] = acc;
    __syncthreads();
    if (threadIdx.x == 0) {
        float s = 0.0f;
#pragma unroll
        for (int i = 0; i < 8; i++) s += red[i];
        out[b * NCLS + c] = s;
    }
}

// ------------------------------------------------------------------
extern "C" void kernel_launch(void* const* d_in, const int* in_sizes, int n_in,
                              void* d_out, int out_size) {
    const float* x   = (const float*)d_in[0];   // [64,28,28]
    const float* pos = (const float*)d_in[1];   // [784,10000]
    const float* lvl = (const float*)d_in[2];   // [256,10000]
    const float* cw  = (const float*)d_in[3];   // [10,10000]
    float* out = (float*)d_out;                 // [64,10]

    pack_bits<<<PIX + LVLS, 256>>>(pos, lvl);
    compute_idx<<<(BATCH * PIX + 255) / 256, 256>>>(x);
    hdc_main<<<dim3((WPAD / 32), BATCH / 8, PCH), 256>>>();
    merge_threshold<<<(BATCH * W313 + 255) / 256, 256>>>();
    classify<<<dim3(BATCH, NCLS), 256>>>(cw, out);
}

// round 3
// speedup vs baseline: 2.4493x; 1.1606x over previous
#include <cuda_runtime.h>
#include <stdint.h>

#define BATCH 64
#define PIX   784
#define DIMS  10000
#define LVLS  256
#define NCLS  10
#define W313  313          // ceil(10000/32)
#define WPAD  320          // padded word count
#define PPC   196          // pixels per warp-chunk (784/4), multiple of 4

// ---- scratch (static device globals; zero-initialized, no allocations) ----
__device__ uint32_t g_pos_bits[PIX  * WPAD];   // sign bits of position  [p][w]
__device__ uint32_t g_lvl_bits[LVLS * WPAD];   // sign bits of levels    [l][w]
__device__ uint8_t  g_idx[BATCH * PIX];        // quantized level index  [b][p]
__device__ uint32_t g_enc[BATCH * WPAD];       // packed enc sign bits (1 = -1)

// ------------------------------------------------------------------
// K0: pack sign bits of position (rows 0..783) and level (rows 784..1039),
//     plus quantize pixel indices (rows 1040..1047).
// ------------------------------------------------------------------
__global__ void __launch_bounds__(256) pack_all(const float* __restrict__ pos,
                                                const float* __restrict__ lvl,
                                                const float* __restrict__ x) {
    int row = blockIdx.x;

    if (row >= PIX + LVLS) {
        // idx quantization: 8 blocks cover BATCH*PIX = 50176 pixels
        int k = row - (PIX + LVLS);
        int base = k * (BATCH * PIX / 8);
        for (int t = threadIdx.x; t < BATCH * PIX / 8; t += 256) {
            int i = __float2int_rn(x[base + t] * 255.0f);   // round-nearest-even
            i = max(0, min(255, i));
            g_idx[base + t] = (uint8_t)i;
        }
        return;
    }

    const float* src;
    uint32_t* dst;
    if (row < PIX) { src = pos + (size_t)row * DIMS; dst = g_pos_bits + row * WPAD; }
    else           { src = lvl + (size_t)(row - PIX) * DIMS; dst = g_lvl_bits + (row - PIX) * WPAD; }

    int lane = threadIdx.x & 31;
    int warp = threadIdx.x >> 5;
    for (int w = warp; w < W313; w += 8) {
        int d = w * 32 + lane;
        float v = (d < DIMS) ? src[d] : 1.0f;   // padding bits -> 0
        uint32_t m = __ballot_sync(0xffffffffu, v < 0.0f);
        if (lane == 0) dst[w] = m;
    }
}

// ------------------------------------------------------------------
// K1: bind+bundle via XOR + CSA bit-plane counters, fused merge+threshold.
// Block = 256 threads: warp (bi, pch) -> batch pair x 4 p-chunks, lane -> word.
// Grid = (10 word-blocks, 32 batch-pairs). Writes g_enc directly.
// ------------------------------------------------------------------
__global__ void __launch_bounds__(256) hdc_encode() {
    __shared__ uint32_t s_lvl[LVLS * 32];      // 32 KB, lane-major gather table
    __shared__ uint32_t s_pl[8][8][32];        // 8 KB, per-warp 8-plane partials

    int lane = threadIdx.x & 31;
    int wid  = threadIdx.x >> 5;
    int bi   = wid >> 2;                       // 0..1
    int pch  = wid & 3;                        // 0..3
    int wblock = blockIdx.x;                   // 0..9
    int bg     = blockIdx.y;                   // 0..31
    int w = wblock * 32 + lane;                // padded word index (< 320)

    // stage level-bit column slice: s_lvl[l*32+lane] = g_lvl_bits[l][w]
    for (int l = wid; l < LVLS; l += 8)
        s_lvl[l * 32 + lane] = g_lvl_bits[l * WPAD + w];
    __syncthreads();

    int b = bg * 2 + bi;
    const uint8_t*  idxr = g_idx + b * PIX + pch * PPC;       // warp-uniform
    const uint32_t* posr = g_pos_bits + (pch * PPC) * WPAD + w;

    // 8-plane counter (max 196 per column)
    uint32_t c0 = 0, c1 = 0, c2 = 0, c3 = 0, c4 = 0, c5 = 0, c6 = 0, c7 = 0;

    #pragma unroll 7
    for (int q = 0; q < PPC / 4; q++) {
        uint32_t i4 = *(const uint32_t*)(idxr + q * 4);
        uint32_t x0 = s_lvl[((i4      ) & 255u) * 32 + lane] ^ posr[(q * 4 + 0) * WPAD];
        uint32_t x1 = s_lvl[((i4 >>  8) & 255u) * 32 + lane] ^ posr[(q * 4 + 1) * WPAD];
        uint32_t x2 = s_lvl[((i4 >> 16) & 255u) * 32 + lane] ^ posr[(q * 4 + 2) * WPAD];
        uint32_t x3 = s_lvl[((i4 >> 24)       ) * 32 + lane] ^ posr[(q * 4 + 3) * WPAD];

        // CSA: x0+x1+x2 -> (h01, l01)
        uint32_t t0  = x0 ^ x1;
        uint32_t l01 = t0 ^ x2;
        uint32_t h01 = (x0 & x1) | (t0 & x2);
        // c0 += l01 + x3
        uint32_t t1 = c0 ^ l01;
        uint32_t ca = (c0 & l01) | (t1 & x3);
        c0 = t1 ^ x3;
        // c1 += h01 + ca
        uint32_t t2 = c1 ^ h01;
        uint32_t cb = (c1 & h01) | (t2 & ca);
        c1 = t2 ^ ca;
        // ripple cb through c2..c7
        uint32_t cr = cb, t;
        t = c2 & cr; c2 ^= cr; cr = t;
        t = c3 & cr; c3 ^= cr; cr = t;
        t = c4 & cr; c4 ^= cr; cr = t;
        t = c5 & cr; c5 ^= cr; cr = t;
        t = c6 & cr; c6 ^= cr; cr = t;
        c7 ^= cr;
    }

    s_pl[wid][0][lane] = c0; s_pl[wid][1][lane] = c1;
    s_pl[wid][2][lane] = c2; s_pl[wid][3][lane] = c3;
    s_pl[wid][4][lane] = c4; s_pl[wid][5][lane] = c5;
    s_pl[wid][6][lane] = c6; s_pl[wid][7][lane] = c7;
    __syncthreads();

    // pch==0 warps merge the 4 partials of their batch and threshold
    if (pch == 0) {
        const uint32_t* p0 = &s_pl[bi * 4 + 0][0][lane];
        const uint32_t* p1 = &s_pl[bi * 4 + 1][0][lane];
        const uint32_t* p2 = &s_pl[bi * 4 + 2][0][lane];
        const uint32_t* p3 = &s_pl[bi * 4 + 3][0][lane];

        uint32_t A[9], B[9], C[10];
        {
            uint32_t carry = 0;
            #pragma unroll
            for (int i = 0; i < 8; i++) {
                uint32_t a = p0[i * 32], bv = p1[i * 32];
                uint32_t t = a ^ bv;
                A[i] = t ^ carry;
                carry = (a & bv) | (t & carry);
            }
            A[8] = carry;
        }
        {
            uint32_t carry = 0;
            #pragma unroll
            for (int i = 0; i < 8; i++) {
                uint32_t a = p2[i * 32], bv = p3[i * 32];
                uint32_t t = a ^ bv;
                B[i] = t ^ carry;
                carry = (a & bv) | (t & carry);
            }
            B[8] = carry;
        }
        {
            uint32_t carry = 0;
            #pragma unroll
            for (int i = 0; i < 9; i++) {
                uint32_t t = A[i] ^ B[i];
                C[i] = t ^ carry;
                carry = (A[i] & B[i]) | (t & carry);
            }
            C[9] = carry;
        }

        // per-column: cnt >= 392 (392 = 0b0110001000) -> enc = -1
        uint32_t gt = 0, eq = 0xffffffffu;
        #pragma unroll
        for (int i = 9; i >= 0; i--) {
            if ((392 >> i) & 1) { eq &= C[i]; }
            else { gt |= eq & C[i]; eq &= ~C[i]; }
        }
        g_enc[b * WPAD + w] = gt | eq;
    }
}

// ------------------------------------------------------------------
// K2: classify — grid (BATCH, NCLS), coalesced W reads, XOR sign flip.
// ------------------------------------------------------------------
__global__ void __launch_bounds__(256) classify(const float* __restrict__ Wc,
                                                float* __restrict__ out) {
    int b = blockIdx.x;
    int c = blockIdx.y;
    const float* wrow = Wc + (size_t)c * DIMS;
    const uint32_t* encp = g_enc + b * WPAD;

    float acc = 0.0f;
    for (int d = threadIdx.x; d < DIMS; d += 256) {
        uint32_t neg  = encp[d >> 5];
        uint32_t flip = ((neg >> (d & 31)) & 1u) << 31;   // sign-bit flip
        acc += __uint_as_float(__float_as_uint(wrow[d]) ^ flip);
    }

    #pragma unroll
    for (int off = 16; off > 0; off >>= 1)
        acc += __shfl_down_sync(0xffffffffu, acc, off);

    __shared__ float red[8];
    int lane = threadIdx.x & 31, warp = threadIdx.x >> 5;
    if (lane == 0) red[warp] = acc;
    __syncthreads();
    if (threadIdx.x == 0) {
        float s = 0.0f;
        #pragma unroll
        for (int i = 0; i < 8; i++) s += red[i];
        out[b * NCLS + c] = s;
    }
}

// ------------------------------------------------------------------
extern "C" void kernel_launch(void* const* d_in, const int* in_sizes, int n_in,
                              void* d_out, int out_size) {
    const float* x   = (const float*)d_in[0];   // [64,28,28]
    const float* pos = (const float*)d_in[1];   // [784,10000]
    const float* lvl = (const float*)d_in[2];   // [256,10000]
    const float* cw  = (const float*)d_in[3];   // [10,10000]
    float* out = (float*)d_out;                 // [64,10]

    pack_all<<<PIX + LVLS + 8, 256>>>(pos, lvl, x);
    hdc_encode<<<dim3(WPAD / 32, BATCH / 2), 256>>>();
    classify<<<dim3(BATCH, NCLS), 256>>>(cw, out);
}

// round 4
// speedup vs baseline: 2.7380x; 1.1179x over previous
#include <cuda_runtime.h>
#include <stdint.h>

#define BATCH 64
#define PIX   784
#define DIMS  10000
#define LVLS  256
#define NCLS  10
#define WPAD  320          // padded words per row (80 groups x 4 words)
#define NGRP  80           // groups of 128 dims per row
#define PPC   196          // pixels per warp-chunk (784/4)

// Packed bit layout (PERMUTED, same for pos/lvl/enc):
//   group g covers dims [g*128, g*128+128)
//   bit b of word (g*4 + j) = sign of dim (g*128 + b*4 + j)
// hdc_encode is layout-agnostic (pure word-wise); classify remaps.

// ---- scratch (static device globals; no allocations) ----
__device__ uint32_t g_pos_bits[PIX  * WPAD];
__device__ uint32_t g_lvl_bits[LVLS * WPAD];
__device__ uint8_t  g_idx[BATCH * PIX];
__device__ uint32_t g_enc[BATCH * WPAD];

// ------------------------------------------------------------------
// K0: pack sign bits (float4 + 4 ballots per 512B) + quantize pixels.
// Blocks 0..1039: one row each (pos rows, then lvl rows).
// Blocks 1040..1047: pixel index quantization.
// ------------------------------------------------------------------
__device__ __forceinline__ float4 ld_or_pos(const float* src, int e) {
    // whole-float4 validity (DIMS % 4 == 0)
    if (e < DIMS) return *(const float4*)(src + e);
    return make_float4(1.0f, 1.0f, 1.0f, 1.0f);   // padding -> bit 0
}

__global__ void __launch_bounds__(256) pack_all(const float* __restrict__ pos,
                                                const float* __restrict__ lvl,
                                                const float* __restrict__ x) {
    int row = blockIdx.x;

    if (row >= PIX + LVLS) {
        int k = row - (PIX + LVLS);
        int base = k * (BATCH * PIX / 8);
        for (int t = threadIdx.x; t < BATCH * PIX / 8; t += 256) {
            int i = __float2int_rn(x[base + t] * 255.0f);
            i = max(0, min(255, i));
            g_idx[base + t] = (uint8_t)i;
        }
        return;
    }

    const float* src;
    uint4* dst;
    if (row < PIX) { src = pos + (size_t)row * DIMS; dst = (uint4*)(g_pos_bits + row * WPAD); }
    else           { src = lvl + (size_t)(row - PIX) * DIMS; dst = (uint4*)(g_lvl_bits + (row - PIX) * WPAD); }

    int lane = threadIdx.x & 31;
    int wid  = threadIdx.x >> 5;

    // warp handles 10 consecutive groups; unrolled x2 for MLP
    int gbase = wid * (NGRP / 8);
    #pragma unroll
    for (int gi = 0; gi < NGRP / 8; gi += 2) {
        int g0 = gbase + gi;
        int g1 = g0 + 1;
        float4 v0 = ld_or_pos(src, g0 * 128 + lane * 4);
        float4 v1 = ld_or_pos(src, g1 * 128 + lane * 4);

        uint4 w0, w1;
        w0.x = __ballot_sync(0xffffffffu, v0.x < 0.0f);
        w0.y = __ballot_sync(0xffffffffu, v0.y < 0.0f);
        w0.z = __ballot_sync(0xffffffffu, v0.z < 0.0f);
        w0.w = __ballot_sync(0xffffffffu, v0.w < 0.0f);
        w1.x = __ballot_sync(0xffffffffu, v1.x < 0.0f);
        w1.y = __ballot_sync(0xffffffffu, v1.y < 0.0f);
        w1.z = __ballot_sync(0xffffffffu, v1.z < 0.0f);
        w1.w = __ballot_sync(0xffffffffu, v1.w < 0.0f);

        if (lane == 0) { dst[g0] = w0; dst[g1] = w1; }
    }
}

// ------------------------------------------------------------------
// K1: bind+bundle via XOR + CSA bit-plane counters, fused merge+threshold.
// Block = 256: warp (bi, pch) -> batch pair x 4 p-chunks, lane -> word.
// Grid = (10 word-blocks, 32 batch-pairs). Writes g_enc directly.
// ------------------------------------------------------------------
__global__ void __launch_bounds__(256) hdc_encode() {
    __shared__ uint32_t s_lvl[LVLS * 32];
    __shared__ uint32_t s_pl[8][8][32];

    int lane = threadIdx.x & 31;
    int wid  = threadIdx.x >> 5;
    int bi   = wid >> 2;
    int pch  = wid & 3;
    int wblock = blockIdx.x;
    int bg     = blockIdx.y;
    int w = wblock * 32 + lane;

    for (int l = wid; l < LVLS; l += 8)
        s_lvl[l * 32 + lane] = g_lvl_bits[l * WPAD + w];
    __syncthreads();

    int b = bg * 2 + bi;
    const uint8_t*  idxr = g_idx + b * PIX + pch * PPC;
    const uint32_t* posr = g_pos_bits + (pch * PPC) * WPAD + w;

    uint32_t c0 = 0, c1 = 0, c2 = 0, c3 = 0, c4 = 0, c5 = 0, c6 = 0, c7 = 0;

    #pragma unroll 7
    for (int q = 0; q < PPC / 4; q++) {
        uint32_t i4 = *(const uint32_t*)(idxr + q * 4);
        uint32_t x0 = s_lvl[((i4      ) & 255u) * 32 + lane] ^ posr[(q * 4 + 0) * WPAD];
        uint32_t x1 = s_lvl[((i4 >>  8) & 255u) * 32 + lane] ^ posr[(q * 4 + 1) * WPAD];
        uint32_t x2 = s_lvl[((i4 >> 16) & 255u) * 32 + lane] ^ posr[(q * 4 + 2) * WPAD];
        uint32_t x3 = s_lvl[((i4 >> 24)       ) * 32 + lane] ^ posr[(q * 4 + 3) * WPAD];

        uint32_t t0  = x0 ^ x1;
        uint32_t l01 = t0 ^ x2;
        uint32_t h01 = (x0 & x1) | (t0 & x2);
        uint32_t t1 = c0 ^ l01;
        uint32_t ca = (c0 & l01) | (t1 & x3);
        c0 = t1 ^ x3;
        uint32_t t2 = c1 ^ h01;
        uint32_t cb = (c1 & h01) | (t2 & ca);
        c1 = t2 ^ ca;
        uint32_t cr = cb, t;
        t = c2 & cr; c2 ^= cr; cr = t;
        t = c3 & cr; c3 ^= cr; cr = t;
        t = c4 & cr; c4 ^= cr; cr = t;
        t = c5 & cr; c5 ^= cr; cr = t;
        t = c6 & cr; c6 ^= cr; cr = t;
        c7 ^= cr;
    }

    s_pl[wid][0][lane] = c0; s_pl[wid][1][lane] = c1;
    s_pl[wid][2][lane] = c2; s_pl[wid][3][lane] = c3;
    s_pl[wid][4][lane] = c4; s_pl[wid][5][lane] = c5;
    s_pl[wid][6][lane] = c6; s_pl[wid][7][lane] = c7;
    __syncthreads();

    if (pch == 0) {
        const uint32_t* p0 = &s_pl[bi * 4 + 0][0][lane];
        const uint32_t* p1 = &s_pl[bi * 4 + 1][0][lane];
        const uint32_t* p2 = &s_pl[bi * 4 + 2][0][lane];
        const uint32_t* p3 = &s_pl[bi * 4 + 3][0][lane];

        uint32_t A[9], B[9], C[10];
        {
            uint32_t carry = 0;
            #pragma unroll
            for (int i = 0; i < 8; i++) {
                uint32_t a = p0[i * 32], bv = p1[i * 32];
                uint32_t t = a ^ bv;
                A[i] = t ^ carry;
                carry = (a & bv) | (t & carry);
            }
            A[8] = carry;
        }
        {
            uint32_t carry = 0;
            #pragma unroll
            for (int i = 0; i < 8; i++) {
                uint32_t a = p2[i * 32], bv = p3[i * 32];
                uint32_t t = a ^ bv;
                B[i] = t ^ carry;
                carry = (a & bv) | (t & carry);
            }
            B[8] = carry;
        }
        {
            uint32_t carry = 0;
            #pragma unroll
            for (int i = 0; i < 9; i++) {
                uint32_t t = A[i] ^ B[i];
                C[i] = t ^ carry;
                carry = (A[i] & B[i]) | (t & carry);
            }
            C[9] = carry;
        }

        // cnt >= 392 (0b0110001000) -> enc = -1
        uint32_t gt = 0, eq = 0xffffffffu;
        #pragma unroll
        for (int i = 9; i >= 0; i--) {
            if ((392 >> i) & 1) { eq &= C[i]; }
            else { gt |= eq & C[i]; eq &= ~C[i]; }
        }
        g_enc[b * WPAD + w] = gt | eq;
    }
}

// ------------------------------------------------------------------
// K2: classify — grid (BATCH, NCLS); remaps permuted bit layout.
// ------------------------------------------------------------------
__global__ void __launch_bounds__(256) classify(const float* __restrict__ Wc,
                                                float* __restrict__ out) {
    int b = blockIdx.x;
    int c = blockIdx.y;
    const float* wrow = Wc + (size_t)c * DIMS;
    const uint32_t* encp = g_enc + b * WPAD;

    float acc = 0.0f;
    for (int d = threadIdx.x; d < DIMS; d += 256) {
        int g = d >> 7, r = d & 127;
        uint32_t neg  = encp[g * 4 + (r & 3)];
        uint32_t flip = ((neg >> (r >> 2)) & 1u) << 31;
        acc += __uint_as_float(__float_as_uint(wrow[d]) ^ flip);
    }

    #pragma unroll
    for (int off = 16; off > 0; off >>= 1)
        acc += __shfl_down_sync(0xffffffffu, acc, off);

    __shared__ float red[8];
    int lane = threadIdx.x & 31, warp = threadIdx.x >> 5;
    if (lane == 0) red[warp] = acc;
    __syncthreads();
    if (threadIdx.x == 0) {
        float s = 0.0f;
        #pragma unroll
        for (int i = 0; i < 8; i++) s += red[i];
        out[b * NCLS + c] = s;
    }
}

// ------------------------------------------------------------------
extern "C" void kernel_launch(void* const* d_in, const int* in_sizes, int n_in,
                              void* d_out, int out_size) {
    const float* x   = (const float*)d_in[0];   // [64,28,28]
    const float* pos = (const float*)d_in[1];   // [784,10000]
    const float* lvl = (const float*)d_in[2];   // [256,10000]
    const float* cw  = (const float*)d_in[3];   // [10,10000]
    float* out = (float*)d_out;                 // [64,10]

    pack_all<<<PIX + LVLS + 8, 256>>>(pos, lvl, x);
    hdc_encode<<<dim3(WPAD / 32, BATCH / 2), 256>>>();
    classify<<<dim3(BATCH, NCLS), 256>>>(cw, out);
}

// round 5
// speedup vs baseline: 3.0974x; 1.1313x over previous
#include <cuda_runtime.h>
#include <stdint.h>

#define BATCH 64
#define PIX   784
#define DIMS  10000
#define LVLS  256
#define NCLS  10
#define WPAD  320          // words per row: 10 groups x 32 words
#define NGRP  10           // groups of 1024 dims
#define PPC   196          // pixels per warp-chunk (784/4)

// Packed bit layout (PERMUTED, identical for pos / lvl / enc):
//   dim d = g*1024 + i*128 + l*4 + j  <->  word (g*32 + l), bit (i*4 + j)
// hdc_encode is word-opaque; classify remaps (cheap: a float4 of W shares
// one word and a contiguous 4-bit nibble).

// ---- scratch (static device globals; no allocations) ----
__device__ uint32_t g_pos_bits[PIX  * WPAD];
__device__ uint32_t g_lvl_bits[LVLS * WPAD];
__device__ uint8_t  g_idx[BATCH * PIX];
__device__ uint32_t g_enc[BATCH * WPAD];

// ------------------------------------------------------------------
// K0: ballot-free sign packing + pixel quantization.
// Blocks 0..1039: one row each (pos rows then lvl rows), 320 threads,
// warp = one 1024-dim group. Blocks 1040..1047: idx quantization.
// ------------------------------------------------------------------
__global__ void __launch_bounds__(320) pack_all(const float* __restrict__ pos,
                                                const float* __restrict__ lvl,
                                                const float* __restrict__ x) {
    int row = blockIdx.x;

    if (row >= PIX + LVLS) {
        int k = row - (PIX + LVLS);
        int base = k * (BATCH * PIX / 8);
        for (int t = threadIdx.x; t < BATCH * PIX / 8; t += 320) {
            int i = __float2int_rn(x[base + t] * 255.0f);   // round-nearest-even
            i = max(0, min(255, i));
            g_idx[base + t] = (uint8_t)i;
        }
        return;
    }

    const float* src;
    uint32_t* dst;
    if (row < PIX) { src = pos + (size_t)row * DIMS; dst = g_pos_bits + row * WPAD; }
    else           { src = lvl + (size_t)(row - PIX) * DIMS; dst = g_lvl_bits + (row - PIX) * WPAD; }

    int lane = threadIdx.x & 31;
    int g    = threadIdx.x >> 5;            // group 0..9

    uint32_t w = 0;
    #pragma unroll
    for (int i = 0; i < 8; i++) {
        int e = g * 1024 + i * 128 + lane * 4;
        // DIMS % 4 == 0 -> float4 fully valid or fully padding
        float4 v = (e < DIMS) ? *(const float4*)(src + e)
                              : make_float4(1.0f, 1.0f, 1.0f, 1.0f);
        uint32_t nib = (__float_as_uint(v.x) >> 31)
                     | ((__float_as_uint(v.y) >> 31) << 1)
                     | ((__float_as_uint(v.z) >> 31) << 2)
                     | ((__float_as_uint(v.w) >> 31) << 3);
        w |= nib << (i * 4);
    }
    dst[g * 32 + lane] = w;                 // coalesced 128B per warp
}

// ------------------------------------------------------------------
// K1: bind+bundle via XOR + CSA bit-plane counters, fused merge+threshold.
// Block = 256: warp (bi, pch) -> batch pair x 4 p-chunks, lane -> word.
// Grid = (10 word-blocks, 32 batch-pairs). Writes g_enc directly.
// ------------------------------------------------------------------
__global__ void __launch_bounds__(256) hdc_encode() {
    __shared__ uint32_t s_lvl[LVLS * 32];
    __shared__ uint32_t s_pl[8][8][32];

    int lane = threadIdx.x & 31;
    int wid  = threadIdx.x >> 5;
    int bi   = wid >> 2;
    int pch  = wid & 3;
    int wblock = blockIdx.x;
    int bg     = blockIdx.y;
    int w = wblock * 32 + lane;

    for (int l = wid; l < LVLS; l += 8)
        s_lvl[l * 32 + lane] = g_lvl_bits[l * WPAD + w];
    __syncthreads();

    int b = bg * 2 + bi;
    const uint8_t*  idxr = g_idx + b * PIX + pch * PPC;
    const uint32_t* posr = g_pos_bits + (pch * PPC) * WPAD + w;

    uint32_t c0 = 0, c1 = 0, c2 = 0, c3 = 0, c4 = 0, c5 = 0, c6 = 0, c7 = 0;

    #pragma unroll 7
    for (int q = 0; q < PPC / 4; q++) {
        uint32_t i4 = *(const uint32_t*)(idxr + q * 4);
        uint32_t x0 = s_lvl[((i4      ) & 255u) * 32 + lane] ^ posr[(q * 4 + 0) * WPAD];
        uint32_t x1 = s_lvl[((i4 >>  8) & 255u) * 32 + lane] ^ posr[(q * 4 + 1) * WPAD];
        uint32_t x2 = s_lvl[((i4 >> 16) & 255u) * 32 + lane] ^ posr[(q * 4 + 2) * WPAD];
        uint32_t x3 = s_lvl[((i4 >> 24)       ) * 32 + lane] ^ posr[(q * 4 + 3) * WPAD];

        uint32_t t0  = x0 ^ x1;
        uint32_t l01 = t0 ^ x2;
        uint32_t h01 = (x0 & x1) | (t0 & x2);
        uint32_t t1 = c0 ^ l01;
        uint32_t ca = (c0 & l01) | (t1 & x3);
        c0 = t1 ^ x3;
        uint32_t t2 = c1 ^ h01;
        uint32_t cb = (c1 & h01) | (t2 & ca);
        c1 = t2 ^ ca;
        uint32_t cr = cb, t;
        t = c2 & cr; c2 ^= cr; cr = t;
        t = c3 & cr; c3 ^= cr; cr = t;
        t = c4 & cr; c4 ^= cr; cr = t;
        t = c5 & cr; c5 ^= cr; cr = t;
        t = c6 & cr; c6 ^= cr; cr = t;
        c7 ^= cr;
    }

    s_pl[wid][0][lane] = c0; s_pl[wid][1][lane] = c1;
    s_pl[wid][2][lane] = c2; s_pl[wid][3][lane] = c3;
    s_pl[wid][4][lane] = c4; s_pl[wid][5][lane] = c5;
    s_pl[wid][6][lane] = c6; s_pl[wid][7][lane] = c7;
    __syncthreads();

    if (pch == 0) {
        const uint32_t* p0 = &s_pl[bi * 4 + 0][0][lane];
        const uint32_t* p1 = &s_pl[bi * 4 + 1][0][lane];
        const uint32_t* p2 = &s_pl[bi * 4 + 2][0][lane];
        const uint32_t* p3 = &s_pl[bi * 4 + 3][0][lane];

        uint32_t A[9], B[9], C[10];
        {
            uint32_t carry = 0;
            #pragma unroll
            for (int i = 0; i < 8; i++) {
                uint32_t a = p0[i * 32], bv = p1[i * 32];
                uint32_t t = a ^ bv;
                A[i] = t ^ carry;
                carry = (a & bv) | (t & carry);
            }
            A[8] = carry;
        }
        {
            uint32_t carry = 0;
            #pragma unroll
            for (int i = 0; i < 8; i++) {
                uint32_t a = p2[i * 32], bv = p3[i * 32];
                uint32_t t = a ^ bv;
                B[i] = t ^ carry;
                carry = (a & bv) | (t & carry);
            }
            B[8] = carry;
        }
        {
            uint32_t carry = 0;
            #pragma unroll
            for (int i = 0; i < 9; i++) {
                uint32_t t = A[i] ^ B[i];
                C[i] = t ^ carry;
                carry = (A[i] & B[i]) | (t & carry);
            }
            C[9] = carry;
        }

        // cnt >= 392 (0b0110001000) -> enc = -1
        uint32_t gt = 0, eq = 0xffffffffu;
        #pragma unroll
        for (int i = 9; i >= 0; i--) {
            if ((392 >> i) & 1) { eq &= C[i]; }
            else { gt |= eq & C[i]; eq &= ~C[i]; }
        }
        g_enc[b * WPAD + w] = gt | eq;
    }
}

// ------------------------------------------------------------------
// K2: classify — grid (BATCH, NCLS); float4 W loads, nibble sign flips.
// ------------------------------------------------------------------
__global__ void __launch_bounds__(256) classify(const float* __restrict__ Wc,
                                                float* __restrict__ out) {
    int b = blockIdx.x;
    int c = blockIdx.y;
    const float* wrow = Wc + (size_t)c * DIMS;
    const uint32_t* encp = g_enc + b * WPAD;

    float acc = 0.0f;
    for (int t = threadIdx.x; t < DIMS / 4; t += 256) {
        int d = t * 4;
        float4 v = *(const float4*)(wrow + d);
        uint32_t word = encp[((d >> 10) << 5) | ((d >> 2) & 31)];
        uint32_t nib  = word >> (((d >> 7) & 7) << 2);   // bits j=0..3
        acc += __uint_as_float(__float_as_uint(v.x) ^ ((nib        & 1u) << 31));
        acc += __uint_as_float(__float_as_uint(v.y) ^ (((nib >> 1) & 1u) << 31));
        acc += __uint_as_float(__float_as_uint(v.z) ^ (((nib >> 2) & 1u) << 31));
        acc += __uint_as_float(__float_as_uint(v.w) ^ (((nib >> 3) & 1u) << 31));
    }

    #pragma unroll
    for (int off = 16; off > 0; off >>= 1)
        acc += __shfl_down_sync(0xffffffffu, acc, off);

    __shared__ float red[8];
    int lane = threadIdx.x & 31, warp = threadIdx.x >> 5;
    if (lane == 0) red[warp] = acc;
    __syncthreads();
    if (threadIdx.x == 0) {
        float s = 0.0f;
        #pragma unroll
        for (int i = 0; i < 8; i++) s += red[i];
        out[b * NCLS + c] = s;
    }
}

// ------------------------------------------------------------------
extern "C" void kernel_launch(void* const* d_in, const int* in_sizes, int n_in,
                              void* d_out, int out_size) {
    const float* x   = (const float*)d_in[0];   // [64,28,28]
    const float* pos = (const float*)d_in[1];   // [784,10000]
    const float* lvl = (const float*)d_in[2];   // [256,10000]
    const float* cw  = (const float*)d_in[3];   // [10,10000]
    float* out = (float*)d_out;                 // [64,10]

    pack_all<<<PIX + LVLS + 8, 320>>>(pos, lvl, x);
    hdc_encode<<<dim3(WPAD / 32, BATCH / 2), 256>>>();
    classify<<<dim3(BATCH, NCLS), 256>>>(cw, out);
}

// round 6
// speedup vs baseline: 3.2826x; 1.0598x over previous
#include <cuda_runtime.h>
#include <stdint.h>

#define BATCH 64
#define PIX   784
#define DIMS  10000
#define LVLS  256
#define NCLS  10
#define WPAD  320          // words per row: 10 groups x 32 words
#define NGRP  10           // groups of 1024 dims per row
#define PPC   196          // pixels per warp-chunk (784/4)

#define NROWS      (PIX + LVLS)          // 1040
#define NTASK_PACK (NROWS * NGRP)        // 10400
#define NTASK_IDX  ((BATCH * PIX) / 128) // 392
#define NTASK_ALL  (NTASK_PACK + NTASK_IDX)
#define PACK_BLOCKS 592                  // 4/SM -> single wave, 4736 warps

// Packed bit layout (PERMUTED, identical for pos / lvl / enc):
//   dim d = g*1024 + i*128 + l*4 + j  <->  word (g*32 + l), bit (i*4 + j)
// hdc_encode is word-opaque; classify remaps (float4 of W shares one word
// and a contiguous 4-bit nibble).

// ---- scratch (static device globals; no allocations) ----
__device__ uint32_t g_pos_bits[PIX  * WPAD];
__device__ uint32_t g_lvl_bits[LVLS * WPAD];
__device__ uint8_t  g_idx[BATCH * PIX];
__device__ uint32_t g_enc[BATCH * WPAD];

// ------------------------------------------------------------------
// K0: grid-stride warp-task pack (single wave, ballot-free) + idx quant.
// Task t < NTASK_PACK: row = t/10, group = t%10 -> pack 32 words.
// Task t >= NTASK_PACK: quantize 128 pixels.
// ------------------------------------------------------------------
__global__ void __launch_bounds__(256) pack_all(const float* __restrict__ pos,
                                                const float* __restrict__ lvl,
                                                const float* __restrict__ x) {
    int lane  = threadIdx.x & 31;
    int gwarp = (blockIdx.x * 256 + threadIdx.x) >> 5;   // 0..4735
    const int nwarps = PACK_BLOCKS * 8;

    for (int task = gwarp; task < NTASK_ALL; task += nwarps) {
        if (task < NTASK_PACK) {
            int row = task / NGRP;
            int g   = task - row * NGRP;

            const float* src;
            uint32_t* dst;
            if (row < PIX) { src = pos + (size_t)row * DIMS; dst = g_pos_bits + row * WPAD; }
            else           { src = lvl + (size_t)(row - PIX) * DIMS; dst = g_lvl_bits + (row - PIX) * WPAD; }

            uint32_t w = 0;
            #pragma unroll
            for (int i = 0; i < 8; i++) {
                int e = g * 1024 + i * 128 + lane * 4;
                // DIMS % 4 == 0 -> float4 fully valid or fully padding
                float4 v = (e < DIMS) ? *(const float4*)(src + e)
                                      : make_float4(1.0f, 1.0f, 1.0f, 1.0f);
                uint32_t nib = (__float_as_uint(v.x) >> 31)
                             | ((__float_as_uint(v.y) >> 31) << 1)
                             | ((__float_as_uint(v.z) >> 31) << 2)
                             | ((__float_as_uint(v.w) >> 31) << 3);
                w |= nib << (i * 4);
            }
            dst[g * 32 + lane] = w;
        } else {
            int t2 = task - NTASK_PACK;          // 0..391, 128 pixels each
            int base = t2 * 128 + lane * 4;
            float4 v = *(const float4*)(x + base);
            uchar4 o;
            int i0 = __float2int_rn(v.x * 255.0f); o.x = (uint8_t)max(0, min(255, i0));
            int i1 = __float2int_rn(v.y * 255.0f); o.y = (uint8_t)max(0, min(255, i1));
            int i2 = __float2int_rn(v.z * 255.0f); o.z = (uint8_t)max(0, min(255, i2));
            int i3 = __float2int_rn(v.w * 255.0f); o.w = (uint8_t)max(0, min(255, i3));
            *(uchar4*)(g_idx + base) = o;
        }
    }
}

// ------------------------------------------------------------------
// K1: bind+bundle via XOR + CSA bit-plane counters, fused merge+threshold.
// Block = 256: warp (bi, pch) -> batch pair x 4 p-chunks, lane -> word.
// Grid = (10 word-blocks, 32 batch-pairs). Writes g_enc directly.
// ------------------------------------------------------------------
__global__ void __launch_bounds__(256) hdc_encode() {
    __shared__ uint32_t s_lvl[LVLS * 32];
    __shared__ uint32_t s_pl[8][8][32];

    int lane = threadIdx.x & 31;
    int wid  = threadIdx.x >> 5;
    int bi   = wid >> 2;
    int pch  = wid & 3;
    int wblock = blockIdx.x;
    int bg     = blockIdx.y;
    int w = wblock * 32 + lane;

    for (int l = wid; l < LVLS; l += 8)
        s_lvl[l * 32 + lane] = g_lvl_bits[l * WPAD + w];
    __syncthreads();

    int b = bg * 2 + bi;
    const uint8_t*  idxr = g_idx + b * PIX + pch * PPC;
    const uint32_t* posr = g_pos_bits + (pch * PPC) * WPAD + w;

    uint32_t c0 = 0, c1 = 0, c2 = 0, c3 = 0, c4 = 0, c5 = 0, c6 = 0, c7 = 0;

    #pragma unroll 7
    for (int q = 0; q < PPC / 4; q++) {
        uint32_t i4 = *(const uint32_t*)(idxr + q * 4);
        uint32_t x0 = s_lvl[((i4      ) & 255u) * 32 + lane] ^ posr[(q * 4 + 0) * WPAD];
        uint32_t x1 = s_lvl[((i4 >>  8) & 255u) * 32 + lane] ^ posr[(q * 4 + 1) * WPAD];
        uint32_t x2 = s_lvl[((i4 >> 16) & 255u) * 32 + lane] ^ posr[(q * 4 + 2) * WPAD];
        uint32_t x3 = s_lvl[((i4 >> 24)       ) * 32 + lane] ^ posr[(q * 4 + 3) * WPAD];

        uint32_t t0  = x0 ^ x1;
        uint32_t l01 = t0 ^ x2;
        uint32_t h01 = (x0 & x1) | (t0 & x2);
        uint32_t t1 = c0 ^ l01;
        uint32_t ca = (c0 & l01) | (t1 & x3);
        c0 = t1 ^ x3;
        uint32_t t2 = c1 ^ h01;
        uint32_t cb = (c1 & h01) | (t2 & ca);
        c1 = t2 ^ ca;
        uint32_t cr = cb, t;
        t = c2 & cr; c2 ^= cr; cr = t;
        t = c3 & cr; c3 ^= cr; cr = t;
        t = c4 & cr; c4 ^= cr; cr = t;
        t = c5 & cr; c5 ^= cr; cr = t;
        t = c6 & cr; c6 ^= cr; cr = t;
        c7 ^= cr;
    }

    s_pl[wid][0][lane] = c0; s_pl[wid][1][lane] = c1;
    s_pl[wid][2][lane] = c2; s_pl[wid][3][lane] = c3;
    s_pl[wid][4][lane] = c4; s_pl[wid][5][lane] = c5;
    s_pl[wid][6][lane] = c6; s_pl[wid][7][lane] = c7;
    __syncthreads();

    if (pch == 0) {
        const uint32_t* p0 = &s_pl[bi * 4 + 0][0][lane];
        const uint32_t* p1 = &s_pl[bi * 4 + 1][0][lane];
        const uint32_t* p2 = &s_pl[bi * 4 + 2][0][lane];
        const uint32_t* p3 = &s_pl[bi * 4 + 3][0][lane];

        uint32_t A[9], B[9], C[10];
        {
            uint32_t carry = 0;
            #pragma unroll
            for (int i = 0; i < 8; i++) {
                uint32_t a = p0[i * 32], bv = p1[i * 32];
                uint32_t t = a ^ bv;
                A[i] = t ^ carry;
                carry = (a & bv) | (t & carry);
            }
            A[8] = carry;
        }
        {
            uint32_t carry = 0;
            #pragma unroll
            for (int i = 0; i < 8; i++) {
                uint32_t a = p2[i * 32], bv = p3[i * 32];
                uint32_t t = a ^ bv;
                B[i] = t ^ carry;
                carry = (a & bv) | (t & carry);
            }
            B[8] = carry;
        }
        {
            uint32_t carry = 0;
            #pragma unroll
            for (int i = 0; i < 9; i++) {
                uint32_t t = A[i] ^ B[i];
                C[i] = t ^ carry;
                carry = (A[i] & B[i]) | (t & carry);
            }
            C[9] = carry;
        }

        // cnt >= 392 (0b0110001000) -> enc = -1
        uint32_t gt = 0, eq = 0xffffffffu;
        #pragma unroll
        for (int i = 9; i >= 0; i--) {
            if ((392 >> i) & 1) { eq &= C[i]; }
            else { gt |= eq & C[i]; eq &= ~C[i]; }
        }
        g_enc[b * WPAD + w] = gt | eq;
    }
}

// ------------------------------------------------------------------
// K2: classify — grid (BATCH, NCLS); float4 W loads, nibble sign flips.
// ------------------------------------------------------------------
__global__ void __launch_bounds__(256) classify(const float* __restrict__ Wc,
                                                float* __restrict__ out) {
    int b = blockIdx.x;
    int c = blockIdx.y;
    const float* wrow = Wc + (size_t)c * DIMS;
    const uint32_t* encp = g_enc + b * WPAD;

    float acc = 0.0f;
    for (int t = threadIdx.x; t < DIMS / 4; t += 256) {
        int d = t * 4;
        float4 v = *(const float4*)(wrow + d);
        uint32_t word = encp[((d >> 10) << 5) | ((d >> 2) & 31)];
        uint32_t nib  = word >> (((d >> 7) & 7) << 2);
        acc += __uint_as_float(__float_as_uint(v.x) ^ ((nib        & 1u) << 31));
        acc += __uint_as_float(__float_as_uint(v.y) ^ (((nib >> 1) & 1u) << 31));
        acc += __uint_as_float(__float_as_uint(v.z) ^ (((nib >> 2) & 1u) << 31));
        acc += __uint_as_float(__float_as_uint(v.w) ^ (((nib >> 3) & 1u) << 31));
    }

    #pragma unroll
    for (int off = 16; off > 0; off >>= 1)
        acc += __shfl_down_sync(0xffffffffu, acc, off);

    __shared__ float red[8];
    int lane = threadIdx.x & 31, warp = threadIdx.x >> 5;
    if (lane == 0) red[warp] = acc;
    __syncthreads();
    if (threadIdx.x == 0) {
        float s = 0.0f;
        #pragma unroll
        for (int i = 0; i < 8; i++) s += red[i];
        out[b * NCLS + c] = s;
    }
}

// ------------------------------------------------------------------
extern "C" void kernel_launch(void* const* d_in, const int* in_sizes, int n_in,
                              void* d_out, int out_size) {
    const float* x   = (const float*)d_in[0];   // [64,28,28]
    const float* pos = (const float*)d_in[1];   // [784,10000]
    const float* lvl = (const float*)d_in[2];   // [256,10000]
    const float* cw  = (const float*)d_in[3];   // [10,10000]
    float* out = (float*)d_out;                 // [64,10]

    pack_all<<<PACK_BLOCKS, 256>>>(pos, lvl, x);
    hdc_encode<<<dim3(WPAD / 32, BATCH / 2), 256>>>();
    classify<<<dim3(BATCH, NCLS), 256>>>(cw, out);
}

// round 7
// speedup vs baseline: 3.3114x; 1.0088x over previous
#include <cuda_runtime.h>
#include <stdint.h>

#define BATCH 64
#define PIX   784
#define DIMS  10000
#define LVLS  256
#define NCLS  10
#define WPAD  320          // words per row: 10 groups x 32 words
#define NGRP  10           // groups of 1024 dims per row
#define PPC   196          // pixels per warp-chunk (784/4)

#define NROWS      (PIX + LVLS)          // 1040
#define NTASK_PACK (NROWS * NGRP)        // 10400
#define NTASK_IDX  ((BATCH * PIX) / 128) // 392
#define NTASK_ALL  (NTASK_PACK + NTASK_IDX)
#define PACK_BLOCKS 1184                 // 8/SM -> single wave, 9472 warps

// Packed bit layout (PERMUTED, identical for pos / lvl / enc):
//   dim d = g*1024 + i*128 + l*4 + j  <->  word (g*32 + l), bit (i*4 + j)
// hdc_encode is word-opaque; classify remaps (float4 of W shares one word
// and a contiguous 4-bit nibble).

// ---- scratch (static device globals; no allocations) ----
__device__ uint32_t g_pos_bits[PIX  * WPAD];
__device__ uint32_t g_lvl_bits[LVLS * WPAD];
__device__ uint8_t  g_idx[BATCH * PIX];
__device__ uint32_t g_enc[BATCH * WPAD];

// ------------------------------------------------------------------
// K0: grid-stride warp-task pack (single wave, ballot-free) + idx quant.
// Task t < NTASK_PACK: row = t/10, group = t%10 -> pack 32 words.
// Task t >= NTASK_PACK: quantize 128 pixels.
// ------------------------------------------------------------------
__global__ void __launch_bounds__(256) pack_all(const float* __restrict__ pos,
                                                const float* __restrict__ lvl,
                                                const float* __restrict__ x) {
    int lane  = threadIdx.x & 31;
    int gwarp = (blockIdx.x * 256 + threadIdx.x) >> 5;   // 0..9471
    const int nwarps = PACK_BLOCKS * 8;

    for (int task = gwarp; task < NTASK_ALL; task += nwarps) {
        if (task < NTASK_PACK) {
            int row = task / NGRP;
            int g   = task - row * NGRP;

            const float* src;
            uint32_t* dst;
            if (row < PIX) { src = pos + (size_t)row * DIMS; dst = g_pos_bits + row * WPAD; }
            else           { src = lvl + (size_t)(row - PIX) * DIMS; dst = g_lvl_bits + (row - PIX) * WPAD; }

            uint32_t w = 0;
            #pragma unroll
            for (int i = 0; i < 8; i++) {
                int e = g * 1024 + i * 128 + lane * 4;
                // DIMS % 4 == 0 -> float4 fully valid or fully padding
                float4 v = (e < DIMS) ? *(const float4*)(src + e)
                                      : make_float4(1.0f, 1.0f, 1.0f, 1.0f);
                uint32_t nib = (__float_as_uint(v.x) >> 31)
                             | ((__float_as_uint(v.y) >> 31) << 1)
                             | ((__float_as_uint(v.z) >> 31) << 2)
                             | ((__float_as_uint(v.w) >> 31) << 3);
                w |= nib << (i * 4);
            }
            dst[g * 32 + lane] = w;
        } else {
            int t2 = task - NTASK_PACK;          // 0..391, 128 pixels each
            int base = t2 * 128 + lane * 4;
            float4 v = *(const float4*)(x + base);
            uchar4 o;
            int i0 = __float2int_rn(v.x * 255.0f); o.x = (uint8_t)max(0, min(255, i0));
            int i1 = __float2int_rn(v.y * 255.0f); o.y = (uint8_t)max(0, min(255, i1));
            int i2 = __float2int_rn(v.z * 255.0f); o.z = (uint8_t)max(0, min(255, i2));
            int i3 = __float2int_rn(v.w * 255.0f); o.w = (uint8_t)max(0, min(255, i3));
            *(uchar4*)(g_idx + base) = o;
        }
    }
}

// ------------------------------------------------------------------
// K1: bind+bundle via XOR + CSA bit-plane counters, fused merge+threshold.
// Block = 256: warp (bi, pch) -> batch pair x 4 p-chunks, lane -> word.
// Grid = (10 word-blocks, 32 batch-pairs). Writes g_enc directly.
// ------------------------------------------------------------------
__global__ void __launch_bounds__(256) hdc_encode() {
    __shared__ uint32_t s_lvl[LVLS * 32];
    __shared__ uint32_t s_pl[8][8][32];

    int lane = threadIdx.x & 31;
    int wid  = threadIdx.x >> 5;
    int bi   = wid >> 2;
    int pch  = wid & 3;
    int wblock = blockIdx.x;
    int bg     = blockIdx.y;
    int w = wblock * 32 + lane;

    for (int l = wid; l < LVLS; l += 8)
        s_lvl[l * 32 + lane] = g_lvl_bits[l * WPAD + w];
    __syncthreads();

    int b = bg * 2 + bi;
    const uint8_t*  idxr = g_idx + b * PIX + pch * PPC;
    const uint32_t* posr = g_pos_bits + (pch * PPC) * WPAD + w;

    uint32_t c0 = 0, c1 = 0, c2 = 0, c3 = 0, c4 = 0, c5 = 0, c6 = 0, c7 = 0;

    #pragma unroll 7
    for (int q = 0; q < PPC / 4; q++) {
        uint32_t i4 = *(const uint32_t*)(idxr + q * 4);
        uint32_t x0 = s_lvl[((i4      ) & 255u) * 32 + lane] ^ posr[(q * 4 + 0) * WPAD];
        uint32_t x1 = s_lvl[((i4 >>  8) & 255u) * 32 + lane] ^ posr[(q * 4 + 1) * WPAD];
        uint32_t x2 = s_lvl[((i4 >> 16) & 255u) * 32 + lane] ^ posr[(q * 4 + 2) * WPAD];
        uint32_t x3 = s_lvl[((i4 >> 24)       ) * 32 + lane] ^ posr[(q * 4 + 3) * WPAD];

        uint32_t t0  = x0 ^ x1;
        uint32_t l01 = t0 ^ x2;
        uint32_t h01 = (x0 & x1) | (t0 & x2);
        uint32_t t1 = c0 ^ l01;
        uint32_t ca = (c0 & l01) | (t1 & x3);
        c0 = t1 ^ x3;
        uint32_t t2 = c1 ^ h01;
        uint32_t cb = (c1 & h01) | (t2 & ca);
        c1 = t2 ^ ca;
        uint32_t cr = cb, t;
        t = c2 & cr; c2 ^= cr; cr = t;
        t = c3 & cr; c3 ^= cr; cr = t;
        t = c4 & cr; c4 ^= cr; cr = t;
        t = c5 & cr; c5 ^= cr; cr = t;
        t = c6 & cr; c6 ^= cr; cr = t;
        c7 ^= cr;
    }

    s_pl[wid][0][lane] = c0; s_pl[wid][1][lane] = c1;
    s_pl[wid][2][lane] = c2; s_pl[wid][3][lane] = c3;
    s_pl[wid][4][lane] = c4; s_pl[wid][5][lane] = c5;
    s_pl[wid][6][lane] = c6; s_pl[wid][7][lane] = c7;
    __syncthreads();

    if (pch == 0) {
        const uint32_t* p0 = &s_pl[bi * 4 + 0][0][lane];
        const uint32_t* p1 = &s_pl[bi * 4 + 1][0][lane];
        const uint32_t* p2 = &s_pl[bi * 4 + 2][0][lane];
        const uint32_t* p3 = &s_pl[bi * 4 + 3][0][lane];

        uint32_t A[9], B[9], C[10];
        {
            uint32_t carry = 0;
            #pragma unroll
            for (int i = 0; i < 8; i++) {
                uint32_t a = p0[i * 32], bv = p1[i * 32];
                uint32_t t = a ^ bv;
                A[i] = t ^ carry;
                carry = (a & bv) | (t & carry);
            }
            A[8] = carry;
        }
        {
            uint32_t carry = 0;
            #pragma unroll
            for (int i = 0; i < 8; i++) {
                uint32_t a = p2[i * 32], bv = p3[i * 32];
                uint32_t t = a ^ bv;
                B[i] = t ^ carry;
                carry = (a & bv) | (t & carry);
            }
            B[8] = carry;
        }
        {
            uint32_t carry = 0;
            #pragma unroll
            for (int i = 0; i < 9; i++) {
                uint32_t t = A[i] ^ B[i];
                C[i] = t ^ carry;
                carry = (A[i] & B[i]) | (t & carry);
            }
            C[9] = carry;
        }

        // cnt >= 392 (0b0110001000) -> enc = -1
        uint32_t gt = 0, eq = 0xffffffffu;
        #pragma unroll
        for (int i = 9; i >= 0; i--) {
            if ((392 >> i) & 1) { eq &= C[i]; }
            else { gt |= eq & C[i]; eq &= ~C[i]; }
        }
        g_enc[b * WPAD + w] = gt | eq;
    }
}

// ------------------------------------------------------------------
// K2: classify — grid (BATCH, NCLS); float4 W loads, nibble sign flips.
// ------------------------------------------------------------------
__global__ void __launch_bounds__(256) classify(const float* __restrict__ Wc,
                                                float* __restrict__ out) {
    int b = blockIdx.x;
    int c = blockIdx.y;
    const float* wrow = Wc + (size_t)c * DIMS;
    const uint32_t* encp = g_enc + b * WPAD;

    float acc = 0.0f;
    for (int t = threadIdx.x; t < DIMS / 4; t += 256) {
        int d = t * 4;
        float4 v = *(const float4*)(wrow + d);
        uint32_t word = encp[((d >> 10) << 5) | ((d >> 2) & 31)];
        uint32_t nib  = word >> (((d >> 7) & 7) << 2);
        acc += __uint_as_float(__float_as_uint(v.x) ^ ((nib        & 1u) << 31));
        acc += __uint_as_float(__float_as_uint(v.y) ^ (((nib >> 1) & 1u) << 31));
        acc += __uint_as_float(__float_as_uint(v.z) ^ (((nib >> 2) & 1u) << 31));
        acc += __uint_as_float(__float_as_uint(v.w) ^ (((nib >> 3) & 1u) << 31));
    }

    #pragma unroll
    for (int off = 16; off > 0; off >>= 1)
        acc += __shfl_down_sync(0xffffffffu, acc, off);

    __shared__ float red[8];
    int lane = threadIdx.x & 31, warp = threadIdx.x >> 5;
    if (lane == 0) red[warp] = acc;
    __syncthreads();
    if (threadIdx.x == 0) {
        float s = 0.0f;
        #pragma unroll
        for (int i = 0; i < 8; i++) s += red[i];
        out[b * NCLS + c] = s;
    }
}

// ------------------------------------------------------------------
extern "C" void kernel_launch(void* const* d_in, const int* in_sizes, int n_in,
                              void* d_out, int out_size) {
    const float* x   = (const float*)d_in[0];   // [64,28,28]
    const float* pos = (const float*)d_in[1];   // [784,10000]
    const float* lvl = (const float*)d_in[2];   // [256,10000]
    const float* cw  = (const float*)d_in[3];   // [10,10000]
    float* out = (float*)d_out;                 // [64,10]

    pack_all<<<PACK_BLOCKS, 256>>>(pos, lvl, x);
    hdc_encode<<<dim3(WPAD / 32, BATCH / 2), 256>>>();
    classify<<<dim3(BATCH, NCLS), 256>>>(cw, out);
}

// round 8
// speedup vs baseline: 3.6211x; 1.0935x over previous
#include <cuda_runtime.h>
#include <stdint.h>

#define BATCH 64
#define PIX   784
#define DIMS  10000
#define LVLS  256
#define NCLS  10
#define WPAD  320          // words per row: 10 groups x 32 words
#define NGRP  10           // groups of 1024 dims per row

#define NROWS      (PIX + LVLS)          // 1040
#define NTASK_PACK (NROWS * NGRP)        // 10400
#define NTASK_IDX  ((BATCH * PIX) / 128) // 392
#define NTASK_ALL  (NTASK_PACK + NTASK_IDX)
#define PACK_BLOCKS 1184                 // single wave

// Packed bit layout (PERMUTED, identical for pos / lvl / enc):
//   dim d = g*1024 + i*128 + l*4 + j  <->  word (g*32 + l), bit (i*4 + j)

// ---- scratch (static device globals; no allocations) ----
__device__ uint32_t g_pos_bits[PIX  * WPAD];
__device__ uint32_t g_lvl_bits[LVLS * WPAD];
__device__ uint8_t  g_idx[BATCH * PIX];
__device__ float    g_pd[BATCH * NCLS * NGRP];   // per-(b,c,wblock) partial logits

// pixel chunk starts (all multiples of 4) and lengths {100x4, 96x4}
__device__ __constant__ int c_start[8] = {0, 100, 200, 300, 400, 496, 592, 688};
__device__ __constant__ int c_len[8]   = {100, 100, 100, 100, 96, 96, 96, 96};

// ------------------------------------------------------------------
// K0: grid-stride warp-task pack (single wave, ballot-free) + idx quant.
// ------------------------------------------------------------------
__global__ void __launch_bounds__(256) pack_all(const float* __restrict__ pos,
                                                const float* __restrict__ lvl,
                                                const float* __restrict__ x) {
    int lane  = threadIdx.x & 31;
    int gwarp = (blockIdx.x * 256 + threadIdx.x) >> 5;
    const int nwarps = PACK_BLOCKS * 8;

    for (int task = gwarp; task < NTASK_ALL; task += nwarps) {
        if (task < NTASK_PACK) {
            int row = task / NGRP;
            int g   = task - row * NGRP;

            const float* src;
            uint32_t* dst;
            if (row < PIX) { src = pos + (size_t)row * DIMS; dst = g_pos_bits + row * WPAD; }
            else           { src = lvl + (size_t)(row - PIX) * DIMS; dst = g_lvl_bits + (row - PIX) * WPAD; }

            uint32_t w = 0;
            #pragma unroll
            for (int i = 0; i < 8; i++) {
                int e = g * 1024 + i * 128 + lane * 4;
                float4 v = (e < DIMS) ? *(const float4*)(src + e)
                                      : make_float4(1.0f, 1.0f, 1.0f, 1.0f);
                uint32_t nib = (__float_as_uint(v.x) >> 31)
                             | ((__float_as_uint(v.y) >> 31) << 1)
                             | ((__float_as_uint(v.z) >> 31) << 2)
                             | ((__float_as_uint(v.w) >> 31) << 3);
                w |= nib << (i * 4);
            }
            dst[g * 32 + lane] = w;
        } else {
            int t2 = task - NTASK_PACK;
            int base = t2 * 128 + lane * 4;
            float4 v = *(const float4*)(x + base);
            uchar4 o;
            int i0 = __float2int_rn(v.x * 255.0f); o.x = (uint8_t)max(0, min(255, i0));
            int i1 = __float2int_rn(v.y * 255.0f); o.y = (uint8_t)max(0, min(255, i1));
            int i2 = __float2int_rn(v.z * 255.0f); o.z = (uint8_t)max(0, min(255, i2));
            int i3 = __float2int_rn(v.w * 255.0f); o.w = (uint8_t)max(0, min(255, i3));
            *(uchar4*)(g_idx + base) = o;
        }
    }
}

// ------------------------------------------------------------------
// K1: fused bind+bundle + threshold + partial classify.
// Grid (10 wblocks, 64 batches), 256 threads. Warp = one pixel chunk.
// s_pl aliases s_lvl after the main loop (smem stays ~32KB).
// ------------------------------------------------------------------
__global__ void __launch_bounds__(256) hdc_encode(const float* __restrict__ Wc) {
    __shared__ uint32_t s_lvl[LVLS * 32];      // 32 KB (reused as s_pl)
    __shared__ uint32_t s_enc[32];
    __shared__ float    s_red[8][NCLS];

    int lane   = threadIdx.x & 31;
    int wid    = threadIdx.x >> 5;             // pixel chunk 0..7
    int wblock = blockIdx.x;                   // 0..9
    int b      = blockIdx.y;                   // 0..63
    int w = wblock * 32 + lane;

    for (int l = wid; l < LVLS; l += 8)
        s_lvl[l * 32 + lane] = g_lvl_bits[l * WPAD + w];
    __syncthreads();

    int pstart = c_start[wid];
    int nq     = c_len[wid] >> 2;              // 25 or 24 quads
    const uint8_t*  idxr = g_idx + b * PIX + pstart;        // 4-aligned
    const uint32_t* posr = g_pos_bits + pstart * WPAD + w;

    // 7-plane counter (max 100 per column)
    uint32_t c0 = 0, c1 = 0, c2 = 0, c3 = 0, c4 = 0, c5 = 0, c6 = 0;

    for (int q = 0; q < nq; q++) {
        uint32_t i4 = *(const uint32_t*)(idxr + q * 4);
        uint32_t x0 = s_lvl[((i4      ) & 255u) * 32 + lane] ^ posr[(q * 4 + 0) * WPAD];
        uint32_t x1 = s_lvl[((i4 >>  8) & 255u) * 32 + lane] ^ posr[(q * 4 + 1) * WPAD];
        uint32_t x2 = s_lvl[((i4 >> 16) & 255u) * 32 + lane] ^ posr[(q * 4 + 2) * WPAD];
        uint32_t x3 = s_lvl[((i4 >> 24)       ) * 32 + lane] ^ posr[(q * 4 + 3) * WPAD];

        uint32_t t0  = x0 ^ x1;
        uint32_t l01 = t0 ^ x2;
        uint32_t h01 = (x0 & x1) | (t0 & x2);
        uint32_t t1 = c0 ^ l01;
        uint32_t ca = (c0 & l01) | (t1 & x3);
        c0 = t1 ^ x3;
        uint32_t t2 = c1 ^ h01;
        uint32_t cb = (c1 & h01) | (t2 & ca);
        c1 = t2 ^ ca;
        uint32_t cr = cb, t;
        t = c2 & cr; c2 ^= cr; cr = t;
        t = c3 & cr; c3 ^= cr; cr = t;
        t = c4 & cr; c4 ^= cr; cr = t;
        t = c5 & cr; c5 ^= cr; cr = t;
        c6 ^= cr;
    }
    __syncthreads();                           // everyone done reading s_lvl

    // alias partial-plane buffer onto s_lvl: layout [warp][plane][lane]
    uint32_t (*s_pl)[7][32] = (uint32_t (*)[7][32])s_lvl;
    s_pl[wid][0][lane] = c0; s_pl[wid][1][lane] = c1;
    s_pl[wid][2][lane] = c2; s_pl[wid][3][lane] = c3;
    s_pl[wid][4][lane] = c4; s_pl[wid][5][lane] = c5;
    s_pl[wid][6][lane] = c6;
    __syncthreads();

    // warp 0: streaming merge of 8 partials (7 planes each) into 10-plane count
    if (wid == 0) {
        uint32_t cur[10];
        #pragma unroll
        for (int i = 0; i < 7; i++) cur[i] = s_pl[0][i][lane];
        #pragma unroll
        for (int i = 7; i < 10; i++) cur[i] = 0;

        #pragma unroll
        for (int k = 1; k < 8; k++) {
            uint32_t carry = 0;
            #pragma unroll
            for (int i = 0; i < 7; i++) {
                uint32_t bv = s_pl[k][i][lane];
                uint32_t a  = cur[i];
                uint32_t t  = a ^ bv;
                cur[i] = t ^ carry;
                carry  = (a & bv) | (t & carry);
            }
            #pragma unroll
            for (int i = 7; i < 10; i++) {
                uint32_t a = cur[i];
                cur[i] = a ^ carry;
                carry  = a & carry;
            }
        }

        // cnt >= 392 (0b0110001000) -> enc = -1
        uint32_t gt = 0, eq = 0xffffffffu;
        #pragma unroll
        for (int i = 9; i >= 0; i--) {
            if ((392 >> i) & 1) { eq &= cur[i]; }
            else { gt |= eq & cur[i]; eq &= ~cur[i]; }
        }
        s_enc[lane] = gt | eq;
    }
    __syncthreads();

    // fused partial classify: thread t covers dims [wblock*1024 + t*4, +4)
    int t4 = threadIdx.x;
    int d  = wblock * 1024 + t4 * 4;
    float acc[NCLS];
    #pragma unroll
    for (int c = 0; c < NCLS; c++) acc[c] = 0.0f;

    if (d < DIMS) {
        uint32_t nib = s_enc[t4 & 31] >> (((t4 >> 5) & 7) << 2);
        uint32_t f0 = (nib        & 1u) << 31;
        uint32_t f1 = ((nib >> 1) & 1u) << 31;
        uint32_t f2 = ((nib >> 2) & 1u) << 31;
        uint32_t f3 = ((nib >> 3) & 1u) << 31;
        #pragma unroll
        for (int c = 0; c < NCLS; c++) {
            float4 v = *(const float4*)(Wc + (size_t)c * DIMS + d);
            float s01 = __uint_as_float(__float_as_uint(v.x) ^ f0)
                      + __uint_as_float(__float_as_uint(v.y) ^ f1);
            float s23 = __uint_as_float(__float_as_uint(v.z) ^ f2)
                      + __uint_as_float(__float_as_uint(v.w) ^ f3);
            acc[c] = s01 + s23;
        }
    }

    // warp reduce each class, then cross-warp via smem (deterministic)
    #pragma unroll
    for (int c = 0; c < NCLS; c++) {
        float v = acc[c];
        #pragma unroll
        for (int off = 16; off > 0; off >>= 1)
            v += __shfl_down_sync(0xffffffffu, v, off);
        if (lane == 0) s_red[wid][c] = v;
    }
    __syncthreads();

    if (wid == 0 && lane < NCLS) {
        float s = 0.0f;
        #pragma unroll
        for (int k = 0; k < 8; k++) s += s_red[k][lane];
        g_pd[(b * NCLS + lane) * NGRP + wblock] = s;
    }
}

// ------------------------------------------------------------------
// K2: reduce partials over wblocks -> out[b][c]
// ------------------------------------------------------------------
__global__ void __launch_bounds__(256) reduce_out(float* __restrict__ out) {
    int tid = blockIdx.x * 256 + threadIdx.x;
    if (tid >= BATCH * NCLS) return;
    const float* p = g_pd + tid * NGRP;
    float s = 0.0f;
    #pragma unroll
    for (int i = 0; i < NGRP; i++) s += p[i];
    out[tid] = s;
}

// ------------------------------------------------------------------
extern "C" void kernel_launch(void* const* d_in, const int* in_sizes, int n_in,
                              void* d_out, int out_size) {
    const float* x   = (const float*)d_in[0];   // [64,28,28]
    const float* pos = (const float*)d_in[1];   // [784,10000]
    const float* lvl = (const float*)d_in[2];   // [256,10000]
    const float* cw  = (const float*)d_in[3];   // [10,10000]
    float* out = (float*)d_out;                 // [64,10]

    pack_all<<<PACK_BLOCKS, 256>>>(pos, lvl, x);
    hdc_encode<<<dim3(NGRP, BATCH), 256>>>(cw);
    reduce_out<<<(BATCH * NCLS + 255) / 256, 256>>>(out);
}

// round 9
// speedup vs baseline: 3.7010x; 1.0221x over previous
#include <cuda_runtime.h>
#include <stdint.h>

#define BATCH 64
#define PIX   784
#define DIMS  10000
#define LVLS  256
#define NCLS  10
#define WPAD  320          // words per row: 10 groups x 32 words
#define NGRP  10           // groups of 1024 dims per row

#define NROWS      (PIX + LVLS)          // 1040
#define NTASK_PACK (NROWS * NGRP)        // 10400
#define NTASK_IDX  ((BATCH * PIX) / 128) // 392
#define NTASK_ALL  (NTASK_PACK + NTASK_IDX)
#define PACK_BLOCKS 592                  // 4/SM @ 64 regs -> single wave

// Packed bit layout (PERMUTED, identical for pos / lvl / enc):
//   dim d = g*1024 + i*128 + l*4 + j  <->  word (g*32 + l), bit (i*4 + j)

// ---- scratch (static device globals; no allocations) ----
__device__ uint32_t g_pos_bits[PIX  * WPAD];
__device__ uint32_t g_lvl_bits[LVLS * WPAD];
__device__ uint8_t  g_idx[BATCH * PIX];
__device__ float    g_pd[BATCH * NCLS * NGRP];   // per-(b,c,wblock) partial logits

// pixel chunk starts (all multiples of 4) and lengths {100x4, 96x4}
__device__ __constant__ int c_start[8] = {0, 100, 200, 300, 400, 496, 592, 688};
__device__ __constant__ int c_len[8]   = {100, 100, 100, 100, 96, 96, 96, 96};

// ------------------------------------------------------------------
// K0: grid-stride warp-task pack + idx quant.
// 64-reg budget (launch_bounds(256,4)) + explicit 8-deep load prefetch
// -> full per-warp MLP instead of register-starved serialization.
// ------------------------------------------------------------------
__global__ void __launch_bounds__(256, 4) pack_all(const float* __restrict__ pos,
                                                   const float* __restrict__ lvl,
                                                   const float* __restrict__ x) {
    int lane  = threadIdx.x & 31;
    int gwarp = (blockIdx.x * 256 + threadIdx.x) >> 5;   // 0..4735
    const int nwarps = PACK_BLOCKS * 8;

    for (int task = gwarp; task < NTASK_ALL; task += nwarps) {
        if (task < NTASK_PACK) {
            int row = task / NGRP;
            int g   = task - row * NGRP;

            const float* src;
            uint32_t* dst;
            if (row < PIX) { src = pos + (size_t)row * DIMS; dst = g_pos_bits + row * WPAD; }
            else           { src = lvl + (size_t)(row - PIX) * DIMS; dst = g_lvl_bits + (row - PIX) * WPAD; }

            // prefetch ALL 8 float4 first (independent, batched by ptxas)
            float4 v[8];
            #pragma unroll
            for (int i = 0; i < 8; i++) {
                int e = g * 1024 + i * 128 + lane * 4;
                v[i] = (e < DIMS) ? *(const float4*)(src + e)
                                  : make_float4(1.0f, 1.0f, 1.0f, 1.0f);
            }

            uint32_t w = 0;
            #pragma unroll
            for (int i = 0; i < 8; i++) {
                uint32_t nib = (__float_as_uint(v[i].x) >> 31)
                             | ((__float_as_uint(v[i].y) >> 31) << 1)
                             | ((__float_as_uint(v[i].z) >> 31) << 2)
                             | ((__float_as_uint(v[i].w) >> 31) << 3);
                w |= nib << (i * 4);
            }
            dst[g * 32 + lane] = w;
        } else {
            int t2 = task - NTASK_PACK;          // 128 pixels each
            int base = t2 * 128 + lane * 4;
            float4 v = *(const float4*)(x + base);
            uchar4 o;
            int i0 = __float2int_rn(v.x * 255.0f); o.x = (uint8_t)max(0, min(255, i0));
            int i1 = __float2int_rn(v.y * 255.0f); o.y = (uint8_t)max(0, min(255, i1));
            int i2 = __float2int_rn(v.z * 255.0f); o.z = (uint8_t)max(0, min(255, i2));
            int i3 = __float2int_rn(v.w * 255.0f); o.w = (uint8_t)max(0, min(255, i3));
            *(uchar4*)(g_idx + base) = o;
        }
    }
}

// ------------------------------------------------------------------
// K1: fused bind+bundle + threshold + partial classify.
// Grid (10 wblocks, 64 batches), 256 threads. Warp = one pixel chunk.
// ------------------------------------------------------------------
__global__ void __launch_bounds__(256) hdc_encode(const float* __restrict__ Wc) {
    __shared__ uint32_t s_lvl[LVLS * 32];      // 32 KB (reused as s_pl)
    __shared__ uint32_t s_enc[32];
    __shared__ float    s_red[8][NCLS];

    int lane   = threadIdx.x & 31;
    int wid    = threadIdx.x >> 5;             // pixel chunk 0..7
    int wblock = blockIdx.x;                   // 0..9
    int b      = blockIdx.y;                   // 0..63
    int w = wblock * 32 + lane;

    for (int l = wid; l < LVLS; l += 8)
        s_lvl[l * 32 + lane] = g_lvl_bits[l * WPAD + w];
    __syncthreads();

    int pstart = c_start[wid];
    int nq     = c_len[wid] >> 2;              // 25 or 24 quads
    const uint8_t*  idxr = g_idx + b * PIX + pstart;        // 4-aligned
    const uint32_t* posr = g_pos_bits + pstart * WPAD + w;

    // 7-plane counter (max 100 per column)
    uint32_t c0 = 0, c1 = 0, c2 = 0, c3 = 0, c4 = 0, c5 = 0, c6 = 0;

    for (int q = 0; q < nq; q++) {
        uint32_t i4 = *(const uint32_t*)(idxr + q * 4);
        uint32_t x0 = s_lvl[((i4      ) & 255u) * 32 + lane] ^ posr[(q * 4 + 0) * WPAD];
        uint32_t x1 = s_lvl[((i4 >>  8) & 255u) * 32 + lane] ^ posr[(q * 4 + 1) * WPAD];
        uint32_t x2 = s_lvl[((i4 >> 16) & 255u) * 32 + lane] ^ posr[(q * 4 + 2) * WPAD];
        uint32_t x3 = s_lvl[((i4 >> 24)       ) * 32 + lane] ^ posr[(q * 4 + 3) * WPAD];

        uint32_t t0  = x0 ^ x1;
        uint32_t l01 = t0 ^ x2;
        uint32_t h01 = (x0 & x1) | (t0 & x2);
        uint32_t t1 = c0 ^ l01;
        uint32_t ca = (c0 & l01) | (t1 & x3);
        c0 = t1 ^ x3;
        uint32_t t2 = c1 ^ h01;
        uint32_t cb = (c1 & h01) | (t2 & ca);
        c1 = t2 ^ ca;
        uint32_t cr = cb, t;
        t = c2 & cr; c2 ^= cr; cr = t;
        t = c3 & cr; c3 ^= cr; cr = t;
        t = c4 & cr; c4 ^= cr; cr = t;
        t = c5 & cr; c5 ^= cr; cr = t;
        c6 ^= cr;
    }
    __syncthreads();                           // everyone done reading s_lvl

    uint32_t (*s_pl)[7][32] = (uint32_t (*)[7][32])s_lvl;
    s_pl[wid][0][lane] = c0; s_pl[wid][1][lane] = c1;
    s_pl[wid][2][lane] = c2; s_pl[wid][3][lane] = c3;
    s_pl[wid][4][lane] = c4; s_pl[wid][5][lane] = c5;
    s_pl[wid][6][lane] = c6;
    __syncthreads();

    if (wid == 0) {
        uint32_t cur[10];
        #pragma unroll
        for (int i = 0; i < 7; i++) cur[i] = s_pl[0][i][lane];
        #pragma unroll
        for (int i = 7; i < 10; i++) cur[i] = 0;

        #pragma unroll
        for (int k = 1; k < 8; k++) {
            uint32_t carry = 0;
            #pragma unroll
            for (int i = 0; i < 7; i++) {
                uint32_t bv = s_pl[k][i][lane];
                uint32_t a  = cur[i];
                uint32_t t  = a ^ bv;
                cur[i] = t ^ carry;
                carry  = (a & bv) | (t & carry);
            }
            #pragma unroll
            for (int i = 7; i < 10; i++) {
                uint32_t a = cur[i];
                cur[i] = a ^ carry;
                carry  = a & carry;
            }
        }

        // cnt >= 392 (0b0110001000) -> enc = -1
        uint32_t gt = 0, eq = 0xffffffffu;
        #pragma unroll
        for (int i = 9; i >= 0; i--) {
            if ((392 >> i) & 1) { eq &= cur[i]; }
            else { gt |= eq & cur[i]; eq &= ~cur[i]; }
        }
        s_enc[lane] = gt | eq;
    }
    __syncthreads();

    // fused partial classify: thread t covers dims [wblock*1024 + t*4, +4)
    int t4 = threadIdx.x;
    int d  = wblock * 1024 + t4 * 4;
    float acc[NCLS];
    #pragma unroll
    for (int c = 0; c < NCLS; c++) acc[c] = 0.0f;

    if (d < DIMS) {
        uint32_t nib = s_enc[t4 & 31] >> (((t4 >> 5) & 7) << 2);
        uint32_t f0 = (nib        & 1u) << 31;
        uint32_t f1 = ((nib >> 1) & 1u) << 31;
        uint32_t f2 = ((nib >> 2) & 1u) << 31;
        uint32_t f3 = ((nib >> 3) & 1u) << 31;
        #pragma unroll
        for (int c = 0; c < NCLS; c++) {
            float4 v = *(const float4*)(Wc + (size_t)c * DIMS + d);
            float s01 = __uint_as_float(__float_as_uint(v.x) ^ f0)
                      + __uint_as_float(__float_as_uint(v.y) ^ f1);
            float s23 = __uint_as_float(__float_as_uint(v.z) ^ f2)
                      + __uint_as_float(__float_as_uint(v.w) ^ f3);
            acc[c] = s01 + s23;
        }
    }

    #pragma unroll
    for (int c = 0; c < NCLS; c++) {
        float v = acc[c];
        #pragma unroll
        for (int off = 16; off > 0; off >>= 1)
            v += __shfl_down_sync(0xffffffffu, v, off);
        if (lane == 0) s_red[wid][c] = v;
    }
    __syncthreads();

    if (wid == 0 && lane < NCLS) {
        float s = 0.0f;
        #pragma unroll
        for (int k = 0; k < 8; k++) s += s_red[k][lane];
        g_pd[(b * NCLS + lane) * NGRP + wblock] = s;
    }
}

// ------------------------------------------------------------------
// K2: reduce partials over wblocks -> out[b][c]
// ------------------------------------------------------------------
__global__ void __launch_bounds__(256) reduce_out(float* __restrict__ out) {
    int tid = blockIdx.x * 256 + threadIdx.x;
    if (tid >= BATCH * NCLS) return;
    const float* p = g_pd + tid * NGRP;
    float s = 0.0f;
    #pragma unroll
    for (int i = 0; i < NGRP; i++) s += p[i];
    out[tid] = s;
}

// ------------------------------------------------------------------
extern "C" void kernel_launch(void* const* d_in, const int* in_sizes, int n_in,
                              void* d_out, int out_size) {
    const float* x   = (const float*)d_in[0];   // [64,28,28]
    const float* pos = (const float*)d_in[1];   // [784,10000]
    const float* lvl = (const float*)d_in[2];   // [256,10000]
    const float* cw  = (const float*)d_in[3];   // [10,10000]
    float* out = (float*)d_out;                 // [64,10]

    pack_all<<<PACK_BLOCKS, 256>>>(pos, lvl, x);
    hdc_encode<<<dim3(NGRP, BATCH), 256>>>(cw);
    reduce_out<<<(BATCH * NCLS + 255) / 256, 256>>>(out);
}